// round 1
// baseline (speedup 1.0000x reference)
#include <cuda_runtime.h>
#include <math.h>

#define BATCH 8
#define SEQ   2048
#define DIM   1024

// Scratch (allocation-free rule: __device__ globals)
__device__ float g_q[(size_t)BATCH * SEQ * DIM];
__device__ float g_k[(size_t)BATCH * SEQ * DIM];
__device__ float g_v[(size_t)BATCH * SEQ * DIM];

#define BM 128
#define BN 128
#define BK 16
#define TM 8
#define TN 8
// 256 threads = 16x16 thread tile grid

// ---------------------------------------------------------------------------
// C[m,n] = scale * sum_k A[m,k] * B[n,k]  (+ bias[n])       "NT" gemm
// A: (M,K) row-major, B: (N,K) row-major. All dims multiples of tile sizes.
// batched over blockIdx.z with the given strides.
// ---------------------------------------------------------------------------
__global__ __launch_bounds__(256) void gemm_nt_kernel(
    const float* __restrict__ Abase, const float* __restrict__ Bbase,
    const float* __restrict__ bias, float* __restrict__ Cbase,
    int M, int N, int K, float scale,
    size_t strideA, size_t strideB, size_t strideC)
{
    __shared__ float As[BK][BM + 4];
    __shared__ float Bs[BK][BN + 4];

    const float* A = Abase + blockIdx.z * strideA + (size_t)blockIdx.y * BM * K;
    const float* B = Bbase + blockIdx.z * strideB + (size_t)blockIdx.x * BN * K;
    float* C = Cbase + blockIdx.z * strideC;

    const int tid = threadIdx.x;
    const int tr = tid >> 4;   // 0..15
    const int tc = tid & 15;   // 0..15

    float acc[TM][TN];
#pragma unroll
    for (int i = 0; i < TM; i++)
#pragma unroll
        for (int j = 0; j < TN; j++) acc[i][j] = 0.0f;

    for (int k0 = 0; k0 < K; k0 += BK) {
#pragma unroll
        for (int i = 0; i < 2; i++) {
            int id  = tid + 256 * i;       // 0..511 float4 slots
            int row = id >> 2;             // 0..127
            int c4  = (id & 3) * 4;        // 0,4,8,12
            float4 a = *(const float4*)(A + (size_t)row * K + k0 + c4);
            As[c4 + 0][row] = a.x; As[c4 + 1][row] = a.y;
            As[c4 + 2][row] = a.z; As[c4 + 3][row] = a.w;
            float4 b = *(const float4*)(B + (size_t)row * K + k0 + c4);
            Bs[c4 + 0][row] = b.x; Bs[c4 + 1][row] = b.y;
            Bs[c4 + 2][row] = b.z; Bs[c4 + 3][row] = b.w;
        }
        __syncthreads();

#pragma unroll
        for (int kk = 0; kk < BK; kk++) {
            float ar[TM], br[TN];
#pragma unroll
            for (int i = 0; i < TM; i++) ar[i] = As[kk][tr * TM + i];
#pragma unroll
            for (int j = 0; j < TN; j++) br[j] = Bs[kk][tc * TN + j];
#pragma unroll
            for (int i = 0; i < TM; i++)
#pragma unroll
                for (int j = 0; j < TN; j++) acc[i][j] += ar[i] * br[j];
        }
        __syncthreads();
    }

    const int crow0 = blockIdx.y * BM + tr * TM;
    const int ccol0 = blockIdx.x * BN + tc * TN;
#pragma unroll
    for (int i = 0; i < TM; i++) {
#pragma unroll
        for (int j = 0; j < TN; j += 4) {
            float4 v;
            v.x = acc[i][j + 0] * scale;
            v.y = acc[i][j + 1] * scale;
            v.z = acc[i][j + 2] * scale;
            v.w = acc[i][j + 3] * scale;
            if (bias) {
                v.x += bias[ccol0 + j + 0];
                v.y += bias[ccol0 + j + 1];
                v.z += bias[ccol0 + j + 2];
                v.w += bias[ccol0 + j + 3];
            }
            *(float4*)(C + (size_t)(crow0 + i) * N + ccol0 + j) = v;
        }
    }
}

// ---------------------------------------------------------------------------
// C[m,n] = sum_k A[m,k] * B[k,n]                             "NN" gemm
// A: (M,K) row-major, B: (K,N) row-major.
// ---------------------------------------------------------------------------
__global__ __launch_bounds__(256) void gemm_nn_kernel(
    const float* __restrict__ Abase, const float* __restrict__ Bbase,
    float* __restrict__ Cbase,
    int M, int N, int K,
    size_t strideA, size_t strideB, size_t strideC)
{
    __shared__ float As[BK][BM + 4];
    __shared__ float Bs[BK][BN + 4];

    const float* A = Abase + blockIdx.z * strideA + (size_t)blockIdx.y * BM * K;
    const float* B = Bbase + blockIdx.z * strideB + (size_t)blockIdx.x * BN;
    float* C = Cbase + blockIdx.z * strideC;

    const int tid = threadIdx.x;
    const int tr = tid >> 4;
    const int tc = tid & 15;

    float acc[TM][TN];
#pragma unroll
    for (int i = 0; i < TM; i++)
#pragma unroll
        for (int j = 0; j < TN; j++) acc[i][j] = 0.0f;

    for (int k0 = 0; k0 < K; k0 += BK) {
        // A tile: transpose into smem (same as NT)
#pragma unroll
        for (int i = 0; i < 2; i++) {
            int id  = tid + 256 * i;
            int row = id >> 2;
            int c4  = (id & 3) * 4;
            float4 a = *(const float4*)(A + (size_t)row * K + k0 + c4);
            As[c4 + 0][row] = a.x; As[c4 + 1][row] = a.y;
            As[c4 + 2][row] = a.z; As[c4 + 3][row] = a.w;
        }
        // B tile: rows are k (16), cols are n (128). Direct copy.
#pragma unroll
        for (int i = 0; i < 2; i++) {
            int id   = tid + 256 * i;       // 512 float4 slots
            int krow = id >> 5;             // 0..15
            int ncol = (id & 31) * 4;       // 0..124
            float4 b = *(const float4*)(B + (size_t)(k0 + krow) * N + ncol);
            *(float4*)&Bs[krow][ncol] = b;
        }
        __syncthreads();

#pragma unroll
        for (int kk = 0; kk < BK; kk++) {
            float ar[TM], br[TN];
#pragma unroll
            for (int i = 0; i < TM; i++) ar[i] = As[kk][tr * TM + i];
#pragma unroll
            for (int j = 0; j < TN; j++) br[j] = Bs[kk][tc * TN + j];
#pragma unroll
            for (int i = 0; i < TM; i++)
#pragma unroll
                for (int j = 0; j < TN; j++) acc[i][j] += ar[i] * br[j];
        }
        __syncthreads();
    }

    const int crow0 = blockIdx.y * BM + tr * TM;
    const int ccol0 = blockIdx.x * BN + tc * TN;
#pragma unroll
    for (int i = 0; i < TM; i++) {
#pragma unroll
        for (int j = 0; j < TN; j += 4) {
            float4 v;
            v.x = acc[i][j + 0]; v.y = acc[i][j + 1];
            v.z = acc[i][j + 2]; v.w = acc[i][j + 3];
            *(float4*)(C + (size_t)(crow0 + i) * N + ccol0 + j) = v;
        }
    }
}

// ---------------------------------------------------------------------------
// In-place row softmax over SEQ=2048 columns. One block (256 thr) per row.
// ---------------------------------------------------------------------------
__global__ __launch_bounds__(256) void softmax_kernel(float* __restrict__ P)
{
    float* p = P + (size_t)blockIdx.x * SEQ;
    const int tid  = threadIdx.x;
    const int lane = tid & 31;
    const int wid  = tid >> 5;

    float4 a = ((const float4*)p)[tid * 2 + 0];
    float4 b = ((const float4*)p)[tid * 2 + 1];
    float x[8] = {a.x, a.y, a.z, a.w, b.x, b.y, b.z, b.w};

    __shared__ float red[8];

    float m = -INFINITY;
#pragma unroll
    for (int i = 0; i < 8; i++) m = fmaxf(m, x[i]);
#pragma unroll
    for (int o = 16; o > 0; o >>= 1) m = fmaxf(m, __shfl_xor_sync(0xffffffffu, m, o));
    if (lane == 0) red[wid] = m;
    __syncthreads();
    float mrow = -INFINITY;
#pragma unroll
    for (int i = 0; i < 8; i++) mrow = fmaxf(mrow, red[i]);
    __syncthreads();

    float s = 0.0f;
#pragma unroll
    for (int i = 0; i < 8; i++) {
        x[i] = expf(x[i] - mrow);
        s += x[i];
    }
#pragma unroll
    for (int o = 16; o > 0; o >>= 1) s += __shfl_xor_sync(0xffffffffu, s, o);
    if (lane == 0) red[wid] = s;
    __syncthreads();
    float total = 0.0f;
#pragma unroll
    for (int i = 0; i < 8; i++) total += red[i];
    const float inv = 1.0f / total;

    float4 o0, o1;
    o0.x = x[0] * inv; o0.y = x[1] * inv; o0.z = x[2] * inv; o0.w = x[3] * inv;
    o1.x = x[4] * inv; o1.y = x[5] * inv; o1.z = x[6] * inv; o1.w = x[7] * inv;
    ((float4*)p)[tid * 2 + 0] = o0;
    ((float4*)p)[tid * 2 + 1] = o1;
}

// ---------------------------------------------------------------------------
extern "C" void kernel_launch(void* const* d_in, const int* in_sizes, int n_in,
                              void* d_out, int out_size)
{
    const float* query = (const float*)d_in[0];
    const float* key   = (const float*)d_in[1];
    const float* value = (const float*)d_in[2];
    const float* Wq    = (const float*)d_in[3];
    const float* bq    = (const float*)d_in[4];
    const float* Wk    = (const float*)d_in[5];
    const float* bk    = (const float*)d_in[6];
    const float* Wv    = (const float*)d_in[7];
    const float* bv    = (const float*)d_in[8];

    float* out_attn = (float*)d_out;                                   // (8,2048,1024)
    float* out_smax = (float*)d_out + (size_t)BATCH * SEQ * DIM;       // (8,2048,2048)

    float *q, *k, *v;
    cudaGetSymbolAddress((void**)&q, g_q);
    cudaGetSymbolAddress((void**)&k, g_k);
    cudaGetSymbolAddress((void**)&v, g_v);

    const int MS = BATCH * SEQ;  // 16384

    // 1) Projections: (16384,1024) = X @ W^T + b
    {
        dim3 grid(DIM / BN, MS / BM, 1);
        gemm_nt_kernel<<<grid, 256>>>(query, Wq, bq, q, MS, DIM, DIM, 1.0f, 0, 0, 0);
        gemm_nt_kernel<<<grid, 256>>>(key,   Wk, bk, k, MS, DIM, DIM, 1.0f, 0, 0, 0);
        gemm_nt_kernel<<<grid, 256>>>(value, Wv, bv, v, MS, DIM, DIM, 1.0f, 0, 0, 0);
    }

    // 2) Scores = 10 * q @ k^T  (batched, straight into softmax output region)
    {
        dim3 grid(SEQ / BN, SEQ / BM, BATCH);
        gemm_nt_kernel<<<grid, 256>>>(q, k, nullptr, out_smax,
                                      SEQ, SEQ, DIM, 10.0f,
                                      (size_t)SEQ * DIM, (size_t)SEQ * DIM,
                                      (size_t)SEQ * SEQ);
    }

    // 3) Row softmax in place
    softmax_kernel<<<BATCH * SEQ, 256>>>(out_smax);

    // 4) out = P @ v  (batched NN)
    {
        dim3 grid(DIM / BN, SEQ / BM, BATCH);
        gemm_nn_kernel<<<grid, 256>>>(out_smax, v, out_attn,
                                      SEQ, DIM, SEQ,
                                      (size_t)SEQ * SEQ, (size_t)SEQ * DIM,
                                      (size_t)SEQ * DIM);
    }
}

// round 2
// speedup vs baseline: 1.0003x; 1.0003x over previous
#include <cuda_runtime.h>
#include <math.h>

#define BATCH 8
#define SEQ   2048
#define DIM   1024

// Scratch (allocation-free rule: __device__ globals)
__device__ float g_q[(size_t)BATCH * SEQ * DIM];
__device__ float g_k[(size_t)BATCH * SEQ * DIM];
__device__ float g_v[(size_t)BATCH * SEQ * DIM];

#define BM 128
#define BN 128
#define BK 16
#define TM 8
#define TN 8
// 256 threads = 16x16 thread tile grid

// ---------------------------------------------------------------------------
// C[m,n] = scale * sum_k A[m,k] * B[n,k]  (+ bias[n])       "NT" gemm
// A: (M,K) row-major, B: (N,K) row-major. All dims multiples of tile sizes.
// batched over blockIdx.z with the given strides.
// ---------------------------------------------------------------------------
__global__ __launch_bounds__(256) void gemm_nt_kernel(
    const float* __restrict__ Abase, const float* __restrict__ Bbase,
    const float* __restrict__ bias, float* __restrict__ Cbase,
    int M, int N, int K, float scale,
    size_t strideA, size_t strideB, size_t strideC)
{
    __shared__ float As[BK][BM + 4];
    __shared__ float Bs[BK][BN + 4];

    const float* A = Abase + blockIdx.z * strideA + (size_t)blockIdx.y * BM * K;
    const float* B = Bbase + blockIdx.z * strideB + (size_t)blockIdx.x * BN * K;
    float* C = Cbase + blockIdx.z * strideC;

    const int tid = threadIdx.x;
    const int tr = tid >> 4;   // 0..15
    const int tc = tid & 15;   // 0..15

    float acc[TM][TN];
#pragma unroll
    for (int i = 0; i < TM; i++)
#pragma unroll
        for (int j = 0; j < TN; j++) acc[i][j] = 0.0f;

    for (int k0 = 0; k0 < K; k0 += BK) {
#pragma unroll
        for (int i = 0; i < 2; i++) {
            int id  = tid + 256 * i;       // 0..511 float4 slots
            int row = id >> 2;             // 0..127
            int c4  = (id & 3) * 4;        // 0,4,8,12
            float4 a = *(const float4*)(A + (size_t)row * K + k0 + c4);
            As[c4 + 0][row] = a.x; As[c4 + 1][row] = a.y;
            As[c4 + 2][row] = a.z; As[c4 + 3][row] = a.w;
            float4 b = *(const float4*)(B + (size_t)row * K + k0 + c4);
            Bs[c4 + 0][row] = b.x; Bs[c4 + 1][row] = b.y;
            Bs[c4 + 2][row] = b.z; Bs[c4 + 3][row] = b.w;
        }
        __syncthreads();

#pragma unroll
        for (int kk = 0; kk < BK; kk++) {
            float ar[TM], br[TN];
#pragma unroll
            for (int i = 0; i < TM; i++) ar[i] = As[kk][tr * TM + i];
#pragma unroll
            for (int j = 0; j < TN; j++) br[j] = Bs[kk][tc * TN + j];
#pragma unroll
            for (int i = 0; i < TM; i++)
#pragma unroll
                for (int j = 0; j < TN; j++) acc[i][j] += ar[i] * br[j];
        }
        __syncthreads();
    }

    const int crow0 = blockIdx.y * BM + tr * TM;
    const int ccol0 = blockIdx.x * BN + tc * TN;
#pragma unroll
    for (int i = 0; i < TM; i++) {
#pragma unroll
        for (int j = 0; j < TN; j += 4) {
            float4 v;
            v.x = acc[i][j + 0] * scale;
            v.y = acc[i][j + 1] * scale;
            v.z = acc[i][j + 2] * scale;
            v.w = acc[i][j + 3] * scale;
            if (bias) {
                v.x += bias[ccol0 + j + 0];
                v.y += bias[ccol0 + j + 1];
                v.z += bias[ccol0 + j + 2];
                v.w += bias[ccol0 + j + 3];
            }
            *(float4*)(C + (size_t)(crow0 + i) * N + ccol0 + j) = v;
        }
    }
}

// ---------------------------------------------------------------------------
// C[m,n] = sum_k A[m,k] * B[k,n]                             "NN" gemm
// A: (M,K) row-major, B: (K,N) row-major.
// ---------------------------------------------------------------------------
__global__ __launch_bounds__(256) void gemm_nn_kernel(
    const float* __restrict__ Abase, const float* __restrict__ Bbase,
    float* __restrict__ Cbase,
    int M, int N, int K,
    size_t strideA, size_t strideB, size_t strideC)
{
    __shared__ float As[BK][BM + 4];
    __shared__ float Bs[BK][BN + 4];

    const float* A = Abase + blockIdx.z * strideA + (size_t)blockIdx.y * BM * K;
    const float* B = Bbase + blockIdx.z * strideB + (size_t)blockIdx.x * BN;
    float* C = Cbase + blockIdx.z * strideC;

    const int tid = threadIdx.x;
    const int tr = tid >> 4;
    const int tc = tid & 15;

    float acc[TM][TN];
#pragma unroll
    for (int i = 0; i < TM; i++)
#pragma unroll
        for (int j = 0; j < TN; j++) acc[i][j] = 0.0f;

    for (int k0 = 0; k0 < K; k0 += BK) {
        // A tile: transpose into smem (same as NT)
#pragma unroll
        for (int i = 0; i < 2; i++) {
            int id  = tid + 256 * i;
            int row = id >> 2;
            int c4  = (id & 3) * 4;
            float4 a = *(const float4*)(A + (size_t)row * K + k0 + c4);
            As[c4 + 0][row] = a.x; As[c4 + 1][row] = a.y;
            As[c4 + 2][row] = a.z; As[c4 + 3][row] = a.w;
        }
        // B tile: rows are k (16), cols are n (128). Direct copy.
#pragma unroll
        for (int i = 0; i < 2; i++) {
            int id   = tid + 256 * i;       // 512 float4 slots
            int krow = id >> 5;             // 0..15
            int ncol = (id & 31) * 4;       // 0..124
            float4 b = *(const float4*)(B + (size_t)(k0 + krow) * N + ncol);
            *(float4*)&Bs[krow][ncol] = b;
        }
        __syncthreads();

#pragma unroll
        for (int kk = 0; kk < BK; kk++) {
            float ar[TM], br[TN];
#pragma unroll
            for (int i = 0; i < TM; i++) ar[i] = As[kk][tr * TM + i];
#pragma unroll
            for (int j = 0; j < TN; j++) br[j] = Bs[kk][tc * TN + j];
#pragma unroll
            for (int i = 0; i < TM; i++)
#pragma unroll
                for (int j = 0; j < TN; j++) acc[i][j] += ar[i] * br[j];
        }
        __syncthreads();
    }

    const int crow0 = blockIdx.y * BM + tr * TM;
    const int ccol0 = blockIdx.x * BN + tc * TN;
#pragma unroll
    for (int i = 0; i < TM; i++) {
#pragma unroll
        for (int j = 0; j < TN; j += 4) {
            float4 v;
            v.x = acc[i][j + 0]; v.y = acc[i][j + 1];
            v.z = acc[i][j + 2]; v.w = acc[i][j + 3];
            *(float4*)(C + (size_t)(crow0 + i) * N + ccol0 + j) = v;
        }
    }
}

// ---------------------------------------------------------------------------
// In-place row softmax over SEQ=2048 columns. One block (256 thr) per row.
// ---------------------------------------------------------------------------
__global__ __launch_bounds__(256) void softmax_kernel(float* __restrict__ P)
{
    float* p = P + (size_t)blockIdx.x * SEQ;
    const int tid  = threadIdx.x;
    const int lane = tid & 31;
    const int wid  = tid >> 5;

    float4 a = ((const float4*)p)[tid * 2 + 0];
    float4 b = ((const float4*)p)[tid * 2 + 1];
    float x[8] = {a.x, a.y, a.z, a.w, b.x, b.y, b.z, b.w};

    __shared__ float red[8];

    float m = -INFINITY;
#pragma unroll
    for (int i = 0; i < 8; i++) m = fmaxf(m, x[i]);
#pragma unroll
    for (int o = 16; o > 0; o >>= 1) m = fmaxf(m, __shfl_xor_sync(0xffffffffu, m, o));
    if (lane == 0) red[wid] = m;
    __syncthreads();
    float mrow = -INFINITY;
#pragma unroll
    for (int i = 0; i < 8; i++) mrow = fmaxf(mrow, red[i]);
    __syncthreads();

    float s = 0.0f;
#pragma unroll
    for (int i = 0; i < 8; i++) {
        x[i] = expf(x[i] - mrow);
        s += x[i];
    }
#pragma unroll
    for (int o = 16; o > 0; o >>= 1) s += __shfl_xor_sync(0xffffffffu, s, o);
    if (lane == 0) red[wid] = s;
    __syncthreads();
    float total = 0.0f;
#pragma unroll
    for (int i = 0; i < 8; i++) total += red[i];
    const float inv = 1.0f / total;

    float4 o0, o1;
    o0.x = x[0] * inv; o0.y = x[1] * inv; o0.z = x[2] * inv; o0.w = x[3] * inv;
    o1.x = x[4] * inv; o1.y = x[5] * inv; o1.z = x[6] * inv; o1.w = x[7] * inv;
    ((float4*)p)[tid * 2 + 0] = o0;
    ((float4*)p)[tid * 2 + 1] = o1;
}

// ---------------------------------------------------------------------------
extern "C" void kernel_launch(void* const* d_in, const int* in_sizes, int n_in,
                              void* d_out, int out_size)
{
    const float* query = (const float*)d_in[0];
    const float* key   = (const float*)d_in[1];
    const float* value = (const float*)d_in[2];
    const float* Wq    = (const float*)d_in[3];
    const float* bq    = (const float*)d_in[4];
    const float* Wk    = (const float*)d_in[5];
    const float* bk    = (const float*)d_in[6];
    const float* Wv    = (const float*)d_in[7];
    const float* bv    = (const float*)d_in[8];

    float* out_attn = (float*)d_out;                                   // (8,2048,1024)
    float* out_smax = (float*)d_out + (size_t)BATCH * SEQ * DIM;       // (8,2048,2048)

    float *q, *k, *v;
    cudaGetSymbolAddress((void**)&q, g_q);
    cudaGetSymbolAddress((void**)&k, g_k);
    cudaGetSymbolAddress((void**)&v, g_v);

    const int MS = BATCH * SEQ;  // 16384

    // 1) Projections: (16384,1024) = X @ W^T + b
    {
        dim3 grid(DIM / BN, MS / BM, 1);
        gemm_nt_kernel<<<grid, 256>>>(query, Wq, bq, q, MS, DIM, DIM, 1.0f, 0, 0, 0);
        gemm_nt_kernel<<<grid, 256>>>(key,   Wk, bk, k, MS, DIM, DIM, 1.0f, 0, 0, 0);
        gemm_nt_kernel<<<grid, 256>>>(value, Wv, bv, v, MS, DIM, DIM, 1.0f, 0, 0, 0);
    }

    // 2) Scores = 10 * q @ k^T  (batched, straight into softmax output region)
    {
        dim3 grid(SEQ / BN, SEQ / BM, BATCH);
        gemm_nt_kernel<<<grid, 256>>>(q, k, nullptr, out_smax,
                                      SEQ, SEQ, DIM, 10.0f,
                                      (size_t)SEQ * DIM, (size_t)SEQ * DIM,
                                      (size_t)SEQ * SEQ);
    }

    // 3) Row softmax in place
    softmax_kernel<<<BATCH * SEQ, 256>>>(out_smax);

    // 4) out = P @ v  (batched NN)
    {
        dim3 grid(DIM / BN, SEQ / BM, BATCH);
        gemm_nn_kernel<<<grid, 256>>>(out_smax, v, out_attn,
                                      SEQ, DIM, SEQ,
                                      (size_t)SEQ * SEQ, (size_t)SEQ * DIM,
                                      (size_t)SEQ * DIM);
    }
}

// round 4
// speedup vs baseline: 1.3334x; 1.3330x over previous
#include <cuda_runtime.h>
#include <math.h>

#define BATCH 8
#define SEQ   2048
#define DIM   1024
#define MSZ   (BATCH*SEQ)
typedef unsigned int u32;

// fp32 scratch (allocation-free rule)
__device__ float g_q [(size_t)MSZ*DIM];
__device__ float g_k [(size_t)MSZ*DIM];
__device__ float g_vt[(size_t)BATCH*DIM*SEQ];   // v transposed: [b][e][s]

// ---------------- tf32 helpers ----------------
__device__ __forceinline__ void cvt2(float x, u32& h, u32& l) {
    asm("cvt.rna.tf32.f32 %0, %1;" : "=r"(h) : "f"(x));
    float r = x - __uint_as_float(h);
    asm("cvt.rna.tf32.f32 %0, %1;" : "=r"(l) : "f"(r));
}
__device__ __forceinline__ void mma8(float* c, const u32* a, const u32* b) {
    asm volatile(
        "mma.sync.aligned.m16n8k8.row.col.f32.tf32.tf32.f32 "
        "{%0,%1,%2,%3}, {%4,%5,%6,%7}, {%8,%9}, {%0,%1,%2,%3};"
        : "+f"(c[0]), "+f"(c[1]), "+f"(c[2]), "+f"(c[3])
        : "r"(a[0]), "r"(a[1]), "r"(a[2]), "r"(a[3]), "r"(b[0]), "r"(b[1]));
}

// ---------------------------------------------------------------------------
// C[m,n] = scale * sum_k A[m,k]*B[n,k] (+ bias)   NT gemm, 3xTF32
// A:(M,K) row-major fp32, B:(N,K) row-major fp32. Tiles 128x128x32.
// 256 threads = 8 warps in 2(m) x 4(n); warp tile 64x32; mma m16n8k8.
// ---------------------------------------------------------------------------
#define LDT 36                      // smem row stride (floats): (36%32)=4 -> frag reads conflict-free
#define TILE_F (128*LDT)            // 4608 floats per tile
#define SMEM_BYTES (4*TILE_F*4)     // 2 bufs * (A+B) = 73728 B

__global__ __launch_bounds__(256, 1) void gemm_tf32(
    const float* __restrict__ A, const float* __restrict__ B,
    const float* __restrict__ bias, int biasRow,
    float* __restrict__ C, int K, float scale,
    size_t sA, size_t sB, size_t sC, int ldc)
{
    extern __shared__ float sm[];   // [buf][A 4608 | B 4608]
    const int tid = threadIdx.x;
    const int wid = tid >> 5, lane = tid & 31;
    const int g = lane >> 2, tig = lane & 3;
    const int wm = (wid >> 2) * 64, wn = (wid & 3) * 32;
    const int z = blockIdx.z;

    const float* Ab = A + z * sA + (size_t)(blockIdx.y * 128) * K;
    const float* Bb = B + z * sB + (size_t)(blockIdx.x * 128) * K;

    // loader indices: 1024 float4 slots per tile, 4 per thread
    const int lrow[4] = { tid >> 3, (tid >> 3) + 32, (tid >> 3) + 64, (tid >> 3) + 96 };
    const int lc4 = (tid & 7) * 4;

    float acc[4][4][4];
#pragma unroll
    for (int mi = 0; mi < 4; mi++)
#pragma unroll
        for (int ni = 0; ni < 4; ni++)
#pragma unroll
            for (int r = 0; r < 4; r++) acc[mi][ni][r] = 0.0f;

    float4 ra[4], rb[4];
    const int nch = K / 32;

    // prologue: chunk 0 -> buf 0
#pragma unroll
    for (int i = 0; i < 4; i++) {
        ra[i] = *(const float4*)(Ab + (size_t)lrow[i] * K + lc4);
        rb[i] = *(const float4*)(Bb + (size_t)lrow[i] * K + lc4);
    }
    {
        float* As = sm; float* Bs = sm + TILE_F;
#pragma unroll
        for (int i = 0; i < 4; i++) {
            *(float4*)(As + lrow[i] * LDT + lc4) = ra[i];
            *(float4*)(Bs + lrow[i] * LDT + lc4) = rb[i];
        }
    }
    __syncthreads();

    for (int c = 0; c < nch; c++) {
        const int p = c & 1;
        if (c + 1 < nch) {
            const int k0 = (c + 1) * 32;
#pragma unroll
            for (int i = 0; i < 4; i++) {
                ra[i] = *(const float4*)(Ab + (size_t)lrow[i] * K + k0 + lc4);
                rb[i] = *(const float4*)(Bb + (size_t)lrow[i] * K + k0 + lc4);
            }
        }

        const float* As = sm + p * 2 * TILE_F;
        const float* Bs = As + TILE_F;
#pragma unroll
        for (int ks = 0; ks < 4; ks++) {
            const int kc = ks * 8 + tig;
            u32 ah[4][4], al[4][4], bh[4][2], bl[4][2];
#pragma unroll
            for (int mi = 0; mi < 4; mi++) {
                const int r0 = (wm + mi * 16 + g) * LDT;
                cvt2(As[r0 + kc],            ah[mi][0], al[mi][0]);
                cvt2(As[r0 + 8 * LDT + kc],  ah[mi][1], al[mi][1]);
                cvt2(As[r0 + kc + 4],        ah[mi][2], al[mi][2]);
                cvt2(As[r0 + 8 * LDT + kc + 4], ah[mi][3], al[mi][3]);
            }
#pragma unroll
            for (int ni = 0; ni < 4; ni++) {
                const int rn = (wn + ni * 8 + g) * LDT;
                cvt2(Bs[rn + kc],     bh[ni][0], bl[ni][0]);
                cvt2(Bs[rn + kc + 4], bh[ni][1], bl[ni][1]);
            }
#pragma unroll
            for (int mi = 0; mi < 4; mi++)
#pragma unroll
                for (int ni = 0; ni < 4; ni++) mma8(acc[mi][ni], ah[mi], bh[ni]);
#pragma unroll
            for (int mi = 0; mi < 4; mi++)
#pragma unroll
                for (int ni = 0; ni < 4; ni++) mma8(acc[mi][ni], ah[mi], bl[ni]);
#pragma unroll
            for (int mi = 0; mi < 4; mi++)
#pragma unroll
                for (int ni = 0; ni < 4; ni++) mma8(acc[mi][ni], al[mi], bh[ni]);
        }

        if (c + 1 < nch) {
            float* Asw = sm + (p ^ 1) * 2 * TILE_F;
            float* Bsw = Asw + TILE_F;
#pragma unroll
            for (int i = 0; i < 4; i++) {
                *(float4*)(Asw + lrow[i] * LDT + lc4) = ra[i];
                *(float4*)(Bsw + lrow[i] * LDT + lc4) = rb[i];
            }
        }
        __syncthreads();
    }

    // epilogue
    float* Cz = C + z * sC;
#pragma unroll
    for (int mi = 0; mi < 4; mi++) {
        const int row0 = blockIdx.y * 128 + wm + mi * 16 + g;
        const float br0 = (bias && biasRow) ? bias[row0] : 0.0f;
        const float br1 = (bias && biasRow) ? bias[row0 + 8] : 0.0f;
#pragma unroll
        for (int ni = 0; ni < 4; ni++) {
            const int col0 = blockIdx.x * 128 + wn + ni * 8 + tig * 2;
            float2 v0, v1;
            v0.x = acc[mi][ni][0] * scale; v0.y = acc[mi][ni][1] * scale;
            v1.x = acc[mi][ni][2] * scale; v1.y = acc[mi][ni][3] * scale;
            if (bias) {
                if (biasRow) { v0.x += br0; v0.y += br0; v1.x += br1; v1.y += br1; }
                else {
                    const float b0 = bias[col0], b1 = bias[col0 + 1];
                    v0.x += b0; v0.y += b1; v1.x += b0; v1.y += b1;
                }
            }
            *(float2*)(Cz + (size_t)row0 * ldc + col0) = v0;
            *(float2*)(Cz + (size_t)(row0 + 8) * ldc + col0) = v1;
        }
    }
}

// ---------------------------------------------------------------------------
// In-place row softmax over SEQ columns. One block (256 thr) per row.
// ---------------------------------------------------------------------------
__global__ __launch_bounds__(256) void softmax_kernel(float* __restrict__ P)
{
    float* p = P + (size_t)blockIdx.x * SEQ;
    const int tid = threadIdx.x, lane = tid & 31, wid = tid >> 5;
    float4 a = ((const float4*)p)[tid * 2 + 0];
    float4 b = ((const float4*)p)[tid * 2 + 1];
    float x[8] = {a.x, a.y, a.z, a.w, b.x, b.y, b.z, b.w};
    __shared__ float red[8];

    float m = -INFINITY;
#pragma unroll
    for (int i = 0; i < 8; i++) m = fmaxf(m, x[i]);
#pragma unroll
    for (int o = 16; o > 0; o >>= 1) m = fmaxf(m, __shfl_xor_sync(0xffffffffu, m, o));
    if (lane == 0) red[wid] = m;
    __syncthreads();
    float mr = -INFINITY;
#pragma unroll
    for (int i = 0; i < 8; i++) mr = fmaxf(mr, red[i]);
    __syncthreads();

    float s = 0.0f;
#pragma unroll
    for (int i = 0; i < 8; i++) { x[i] = expf(x[i] - mr); s += x[i]; }
#pragma unroll
    for (int o = 16; o > 0; o >>= 1) s += __shfl_xor_sync(0xffffffffu, s, o);
    if (lane == 0) red[wid] = s;
    __syncthreads();
    float tot = 0.0f;
#pragma unroll
    for (int i = 0; i < 8; i++) tot += red[i];
    const float inv = 1.0f / tot;

    float4 o0, o1;
    o0.x = x[0] * inv; o0.y = x[1] * inv; o0.z = x[2] * inv; o0.w = x[3] * inv;
    o1.x = x[4] * inv; o1.y = x[5] * inv; o1.z = x[6] * inv; o1.w = x[7] * inv;
    ((float4*)p)[tid * 2 + 0] = o0;
    ((float4*)p)[tid * 2 + 1] = o1;
}

// ---------------------------------------------------------------------------
extern "C" void kernel_launch(void* const* d_in, const int* in_sizes, int n_in,
                              void* d_out, int out_size)
{
    const float* query = (const float*)d_in[0];
    const float* key   = (const float*)d_in[1];
    const float* value = (const float*)d_in[2];
    const float* Wq = (const float*)d_in[3]; const float* bq = (const float*)d_in[4];
    const float* Wk = (const float*)d_in[5]; const float* bk = (const float*)d_in[6];
    const float* Wv = (const float*)d_in[7]; const float* bv = (const float*)d_in[8];

    float* out_attn = (float*)d_out;
    float* out_smax = (float*)d_out + (size_t)MSZ * DIM;

    float *q, *k, *vt;
    cudaGetSymbolAddress((void**)&q,  g_q);
    cudaGetSymbolAddress((void**)&k,  g_k);
    cudaGetSymbolAddress((void**)&vt, g_vt);

    cudaFuncSetAttribute(gemm_tf32, cudaFuncAttributeMaxDynamicSharedMemorySize, SMEM_BYTES);

    // 1) q = query @ Wq^T + bq ; k = key @ Wk^T + bk
    {
        dim3 grid(DIM / 128, MSZ / 128, 1);
        gemm_tf32<<<grid, 256, SMEM_BYTES>>>(query, Wq, bq, 0, q, DIM, 1.0f, 0, 0, 0, DIM);
        gemm_tf32<<<grid, 256, SMEM_BYTES>>>(key,   Wk, bk, 0, k, DIM, 1.0f, 0, 0, 0, DIM);
    }
    // 2) vT[b,e,s] = Wv[e,:] . value[b,s,:] + bv[e]  (bias per-row)
    {
        dim3 grid(SEQ / 128, DIM / 128, BATCH);
        gemm_tf32<<<grid, 256, SMEM_BYTES>>>(Wv, value, bv, 1, vt, DIM, 1.0f,
                                             0, (size_t)SEQ * DIM, (size_t)DIM * SEQ, SEQ);
    }
    // 3) scores = 10 * q @ k^T
    {
        dim3 grid(SEQ / 128, SEQ / 128, BATCH);
        gemm_tf32<<<grid, 256, SMEM_BYTES>>>(q, k, nullptr, 0, out_smax, DIM, 10.0f,
                                             (size_t)SEQ * DIM, (size_t)SEQ * DIM,
                                             (size_t)SEQ * SEQ, SEQ);
    }
    // 4) softmax in place
    softmax_kernel<<<MSZ, 256>>>(out_smax);
    // 5) out = P @ vT^T   (NT: C[s,e] = P[s,:] . vT[e,:])
    {
        dim3 grid(DIM / 128, SEQ / 128, BATCH);
        gemm_tf32<<<grid, 256, SMEM_BYTES>>>(out_smax, vt, nullptr, 0, out_attn, SEQ, 1.0f,
                                             (size_t)SEQ * SEQ, (size_t)DIM * SEQ,
                                             (size_t)SEQ * DIM, DIM);
    }
}